// round 16
// baseline (speedup 1.0000x reference)
#include <cuda_runtime.h>
#include <cuda_bf16.h>
#include <math.h>
#include <stdint.h>

#define G    64
#define NN   1024
#define KTOP 128
#define CH   8                               // graphs per chunk
#define NE   (G * NN * 32)                   // 2,097,152 edges
#define MATS ((size_t)NN * NN)
#define CTOT ((size_t)CH * MATS)             // 8,388,608 elems per chunk-buffer
#define OUTM ((size_t)G * NN * KTOP)

// pitch-48 smem tiles: 16B-aligned and conflict-free ldmatrix (stride 12 banks)
#define PITCH 48
#define TTILE (128 * PITCH)                  // 6144 bytes per split-term tile

// fp32 rotating buffers (3 x 32MB) + bf16 split arrays (9 x 16MB = 144MB)
// directed graph => NO symmetry: separate A-form and transposed B-form splits
__device__ __align__(16) float g_scratch[3 * CTOT];
__device__ __align__(16) float g_dis[CH * NN];
__device__ __align__(16) __nv_bfloat16 g_pa_h[CTOT],  g_pa_m[CTOT],  g_pa_l[CTOT];   // P (M,K)
__device__ __align__(16) __nv_bfloat16 g_pbt_h[CTOT], g_pbt_m[CTOT], g_pbt_l[CTOT];  // P^T (N,K)
__device__ __align__(16) __nv_bfloat16 g_sbt_h[CTOT], g_sbt_m[CTOT], g_sbt_l[CTOT];  // S^T (N,K)

__device__ __forceinline__ float* BUF(int i) { return g_scratch + (size_t)i * CTOT; }

__device__ __forceinline__ uint32_t smem_u32(const void* p) {
    uint32_t a;
    asm("{ .reg .u64 t; cvta.to.shared.u64 t, %1; cvt.u32.u64 %0, t; }" : "=r"(a) : "l"(p));
    return a;
}

// ---------------------------------------------------------------------------
__global__ void out_init_kernel(float* __restrict__ out)
{
    size_t i  = (size_t)blockIdx.x * blockDim.x + threadIdx.x;
    size_t st = (size_t)gridDim.x * blockDim.x;
    for (; i < OUTM; i += st) {
        int g = (int)(i / (NN * KTOP));
        int j = (int)((i / KTOP) & 1023);
        float v = (float)((g << 10) + j);
        out[i] = v; out[OUTM + i] = v;
    }
}

__global__ void zero_kernel(int bi)
{
    float4* p = (float4*)BUF(bi);
    size_t i  = (size_t)blockIdx.x * blockDim.x + threadIdx.x;
    size_t st = (size_t)gridDim.x * blockDim.x;
    float4 z = make_float4(0.f, 0.f, 0.f, 0.f);
    for (size_t n4 = CTOT / 4; i < n4; i += st) p[i] = z;
}

__global__ void edge_kernel(const int* __restrict__ ei, int bi, int c0)
{
    float* A = BUF(bi);
    int e = blockIdx.x * blockDim.x + threadIdx.x;
    if (e >= NE) return;
    int src = ei[e];
    if (src < 0 || src >= G * NN) return;
    int g = src >> 10;
    if (g < c0 || g >= c0 + CH) return;
    int dst = ei[NE + e];
    A[((size_t)(src - (c0 << 10)) << 10) + (dst & 1023)] = 1.0f;
}

__global__ void diag_kernel(int bi)
{
    float* A = BUF(bi);
    int idx = blockIdx.x * blockDim.x + threadIdx.x;
    if (idx >= CH * NN) return;
    A[((size_t)idx << 10) + (idx & 1023)] += 1.0f;
}

__global__ void deg_kernel(int bi)
{
    __shared__ float sm[8];
    const float* r = BUF(bi) + ((size_t)blockIdx.x << 10);
    float s = 0.f;
    for (int j = threadIdx.x; j < NN; j += 256) s += r[j];
    #pragma unroll
    for (int o = 16; o; o >>= 1) s += __shfl_down_sync(0xffffffffu, s, o);
    if ((threadIdx.x & 31) == 0) sm[threadIdx.x >> 5] = s;
    __syncthreads();
    if (threadIdx.x == 0) {
        float tot = 0.f;
        #pragma unroll
        for (int w = 0; w < 8; w++) tot += sm[w];
        g_dis[blockIdx.x] = 1.0f / sqrtf(tot);
    }
}

// T = dis_i * A * dis_j (in place);  S = I + 0.95*T
__global__ void build_ts_kernel(int ba, int bs)
{
    float* A = BUF(ba);
    float* S = BUF(bs);
    size_t idx = (size_t)blockIdx.x * 256 + threadIdx.x;
    if (idx >= CTOT) return;
    int    j     = (int)(idx & 1023);
    size_t rowid = idx >> 10;
    int    i     = (int)(rowid & 1023);
    int    gb    = (int)((rowid >> 10) << 10);
    float t = g_dis[rowid] * A[idx] * g_dis[gb + j];
    A[idx] = t;
    S[idx] = 0.95f * t + ((i == j) ? 1.0f : 0.0f);
}

// ---------------------------------------------------------------------------
// bf16 3-term split x = h + m + l (error ~2^-26 x)
// ---------------------------------------------------------------------------
__device__ __forceinline__ void split3(float x, unsigned short& hh,
                                       unsigned short& mm, unsigned short& ll)
{
    __nv_bfloat16 h = __float2bfloat16(x);
    float r = x - __bfloat162float(h);
    __nv_bfloat16 m = __float2bfloat16(r);
    r -= __bfloat162float(m);
    __nv_bfloat16 l = __float2bfloat16(r);
    hh = __bfloat16_as_ushort(h);
    mm = __bfloat16_as_ushort(m);
    ll = __bfloat16_as_ushort(l);
}

// P -> A-form (direct) + B-form (transposed) splits
__global__ void split_p_kernel(int bi)
{
    __shared__ float tile[32][33];
    int gph = blockIdx.z;
    int i0 = blockIdx.y * 32, j0 = blockIdx.x * 32;
    const float* Pg = BUF(bi) + ((size_t)gph << 20);
    size_t gb = (size_t)gph << 20;
    int x = threadIdx.x, y = threadIdx.y;     // 32 x 8
    #pragma unroll
    for (int r = 0; r < 32; r += 8) {
        float v = Pg[(size_t)(i0 + y + r) * NN + j0 + x];
        tile[y + r][x] = v;
        unsigned short h, m, l; split3(v, h, m, l);
        size_t o = gb + (size_t)(i0 + y + r) * NN + j0 + x;
        ((unsigned short*)g_pa_h)[o] = h;
        ((unsigned short*)g_pa_m)[o] = m;
        ((unsigned short*)g_pa_l)[o] = l;
    }
    __syncthreads();
    #pragma unroll
    for (int r = 0; r < 32; r += 8) {
        unsigned short h, m, l; split3(tile[x][y + r], h, m, l);   // = P[i0+x][j0+y+r]
        size_t o = gb + (size_t)(j0 + y + r) * NN + i0 + x;        // P^T[j][i]
        ((unsigned short*)g_pbt_h)[o] = h;
        ((unsigned short*)g_pbt_m)[o] = m;
        ((unsigned short*)g_pbt_l)[o] = l;
    }
}

// S -> B-form (transposed) splits only
__global__ void split_s_kernel(int bi)
{
    __shared__ float tile[32][33];
    int gph = blockIdx.z;
    int i0 = blockIdx.y * 32, j0 = blockIdx.x * 32;
    const float* Sg = BUF(bi) + ((size_t)gph << 20);
    size_t gb = (size_t)gph << 20;
    int x = threadIdx.x, y = threadIdx.y;
    #pragma unroll
    for (int r = 0; r < 32; r += 8)
        tile[y + r][x] = Sg[(size_t)(i0 + y + r) * NN + j0 + x];
    __syncthreads();
    #pragma unroll
    for (int r = 0; r < 32; r += 8) {
        unsigned short h, m, l; split3(tile[x][y + r], h, m, l);
        size_t o = gb + (size_t)(j0 + y + r) * NN + i0 + x;
        ((unsigned short*)g_sbt_h)[o] = h;
        ((unsigned short*)g_sbt_m)[o] = m;
        ((unsigned short*)g_sbt_l)[o] = l;
    }
}

// ---------------------------------------------------------------------------
// HMMA bf16 3-split GEMM: D = alpha*(P*X) + C
// B-form tiles are X^T stored n-major => NON-trans ldmatrix.x2 yields the
// canonical col-major B fragment: lane l -> (n=l>>2, k=(l&3)*2,+1)
// ---------------------------------------------------------------------------
__device__ __forceinline__ void ldsm_x4(uint32_t* a, uint32_t addr) {
    asm volatile("ldmatrix.sync.aligned.m8n8.x4.shared.b16 {%0,%1,%2,%3}, [%4];"
                 : "=r"(a[0]), "=r"(a[1]), "=r"(a[2]), "=r"(a[3]) : "r"(addr));
}
__device__ __forceinline__ void ldsm_x2(uint32_t* b, uint32_t addr) {
    asm volatile("ldmatrix.sync.aligned.m8n8.x2.shared.b16 {%0,%1}, [%2];"
                 : "=r"(b[0]), "=r"(b[1]) : "r"(addr));
}
__device__ __forceinline__ void mma_bf16(float* c, const uint32_t* a, const uint32_t* b) {
    asm volatile("mma.sync.aligned.m16n8k16.row.col.f32.bf16.bf16.f32 "
                 "{%0,%1,%2,%3}, {%4,%5,%6,%7}, {%8,%9}, {%0,%1,%2,%3};"
                 : "+f"(c[0]), "+f"(c[1]), "+f"(c[2]), "+f"(c[3])
                 : "r"(a[0]), "r"(a[1]), "r"(a[2]), "r"(a[3]), "r"(b[0]), "r"(b[1]));
}

__global__ __launch_bounds__(256, 2)
void gemm_hmma(int selB, int bc, int bd, float alpha)
{
    __shared__ __align__(16) char smA[3 * TTILE];   // 3 terms x 128 rows x 48B
    __shared__ __align__(16) char smB[3 * TTILE];

    const int tid  = threadIdx.x;
    const int lane = tid & 31;
    const int w    = tid >> 5;
    const int wm   = w & 1;
    const int wn   = w >> 1;
    const int g    = blockIdx.z;
    const int m0   = blockIdx.y * 128, n0 = blockIdx.x * 128;
    const size_t gb = (size_t)g * MATS;

    const __nv_bfloat16* At[3] = { g_pa_h + gb, g_pa_m + gb, g_pa_l + gb };
    const __nv_bfloat16* Bt[3] = { (selB ? g_sbt_h : g_pbt_h) + gb,
                                   (selB ? g_sbt_m : g_pbt_m) + gb,
                                   (selB ? g_sbt_l : g_pbt_l) + gb };
    float*       D = BUF(bd) + gb;
    const float* C = (bc >= 0) ? (BUF(bc) + gb) : (const float*)0;

    const uint32_t sA = smem_u32(smA), sB = smem_u32(smB);

    float acc[4][4][4];
    #pragma unroll
    for (int i = 0; i < 4; i++)
        #pragma unroll
        for (int j = 0; j < 4; j++)
            #pragma unroll
            for (int k = 0; k < 4; k++) acc[i][j][k] = 0.0f;

    const int PA[6] = {0, 0, 1, 0, 2, 1};
    const int PB[6] = {0, 1, 0, 2, 0, 1};

    const uint32_t aOff = (uint32_t)(lane & 15) * PITCH + (uint32_t)(lane >> 4) * 16;
    const uint32_t bOff = (uint32_t)(lane & 7) * PITCH + (uint32_t)((lane >> 3) & 1) * 16;

    for (int ch = 0; ch < 64; ch++) {
        const int kb = ch << 4;
        #pragma unroll
        for (int l = 0; l < 3; l++) {
            int idx  = tid + l * 256;
            int term = idx >> 8;
            int rq   = idx & 255;
            int r    = rq >> 1, q = rq & 1;
            uint32_t so = (uint32_t)(term * TTILE + r * PITCH + q * 16);
            *(uint4*)(smA + so) = *(const uint4*)(At[term] + (size_t)(m0 + r) * NN + kb + q * 8);
            *(uint4*)(smB + so) = *(const uint4*)(Bt[term] + (size_t)(n0 + r) * NN + kb + q * 8);
        }
        __syncthreads();

        #pragma unroll
        for (int pr = 0; pr < 6; pr++) {
            uint32_t a[4][4], b[4][2];
            #pragma unroll
            for (int mi = 0; mi < 4; mi++)
                ldsm_x4(a[mi], sA + PA[pr] * TTILE + (wm * 64 + mi * 16) * PITCH + aOff);
            #pragma unroll
            for (int ni = 0; ni < 4; ni++)
                ldsm_x2(b[ni], sB + PB[pr] * TTILE + (wn * 32 + ni * 8) * PITCH + bOff);
            #pragma unroll
            for (int mi = 0; mi < 4; mi++)
                #pragma unroll
                for (int ni = 0; ni < 4; ni++)
                    mma_bf16(acc[mi][ni], a[mi], b[ni]);
        }
        __syncthreads();
    }

    #pragma unroll
    for (int mi = 0; mi < 4; mi++) {
        int row = m0 + wm * 64 + mi * 16 + (lane >> 2);
        #pragma unroll
        for (int ni = 0; ni < 4; ni++) {
            int col = n0 + wn * 32 + ni * 8 + (lane & 3) * 2;
            size_t o0 = (size_t)row * NN + col;
            size_t o1 = o0 + 8 * NN;
            float2 v0 = make_float2(alpha * acc[mi][ni][0], alpha * acc[mi][ni][1]);
            float2 v1 = make_float2(alpha * acc[mi][ni][2], alpha * acc[mi][ni][3]);
            if (C) {
                float2 c0 = *(const float2*)(C + o0);
                float2 c1 = *(const float2*)(C + o1);
                v0.x += c0.x; v0.y += c0.y; v1.x += c1.x; v1.y += c1.y;
            }
            *(float2*)(D + o0) = v0;
            *(float2*)(D + o1) = v1;
        }
    }
}

// ---------------------------------------------------------------------------
__global__ void transpose_kernel(int bs, int bt)
{
    __shared__ float tile[32][33];
    int g  = blockIdx.z;
    int i0 = blockIdx.y * 32, j0 = blockIdx.x * 32;
    const float* Sg = BUF(bs) + ((size_t)g << 20);
    float*       Tg = BUF(bt) + ((size_t)g << 20);
    int x = threadIdx.x, y = threadIdx.y;
    #pragma unroll
    for (int r = 0; r < 32; r += 8)
        tile[y + r][x] = Sg[(size_t)(i0 + y + r) * NN + j0 + x];
    __syncthreads();
    #pragma unroll
    for (int r = 0; r < 32; r += 8)
        Tg[(size_t)(j0 + y + r) * NN + i0 + x] = tile[x][y + r];
}

// per-column top-128 on the transposed matrix (rows of S^T = columns of S)
__global__ __launch_bounds__(512)
void topk_kernel(int bt, float* __restrict__ out, int c0)
{
    __shared__ unsigned long long key[1024];
    const int col = blockIdx.x;
    const int gg  = c0 + (col >> 10);
    const float* row = BUF(bt) + ((size_t)col << 10);
    const int t = threadIdx.x;

    for (int i = t; i < 1024; i += 512) {
        unsigned vb = __float_as_uint(row[i]);
        key[i] = ((unsigned long long)vb << 32) | (unsigned)(1023 - i);
    }
    __syncthreads();
    for (int k = 2; k <= 1024; k <<= 1) {
        for (int j = k >> 1; j > 0; j >>= 1) {
            unsigned idx = ((t & ~(j - 1)) << 1) | (t & (j - 1));
            unsigned pi  = idx | j;
            bool desc = ((idx & k) == 0);
            unsigned long long a = key[idx], b = key[pi];
            if ((a < b) == desc) { key[idx] = b; key[pi] = a; }
            __syncthreads();
        }
    }
    if (t < KTOP) {
        unsigned long long kk = key[t];
        int i = 1023 - (int)(kk & 0xFFFFFFFFu);
        size_t base = ((size_t)(c0 << 10) + col) * KTOP + t;
        out[base]        = (float)((gg << 10) + i);
        out[OUTM + base] = (float)((gg << 10) + (col & 1023));
    }
}

// ---------------------------------------------------------------------------
extern "C" void kernel_launch(void* const* d_in, const int* in_sizes, int n_in,
                              void* d_out, int out_size)
{
    (void)out_size;
    const int* ei = (const int*)d_in[0];
    for (int i = 0; i < n_in; i++)
        if (in_sizes[i] == 2 * NE) { ei = (const int*)d_in[i]; break; }
    float* out = (float*)d_out;

    out_init_kernel<<<4096, 256>>>(out);

    dim3 gg(8, 8, CH);
    dim3 sg(32, 32, CH), sb(32, 8);

    for (int c0 = 0; c0 < G; c0 += CH) {
        zero_kernel    <<<8192, 256>>>(0);
        edge_kernel    <<<NE / 256, 256>>>(ei, 0, c0);
        diag_kernel    <<<CH * NN / 256, 256>>>(0);
        deg_kernel     <<<CH * NN, 256>>>(0);
        build_ts_kernel<<<(unsigned)(CTOT / 256), 256>>>(0, 1);   // T in b0, S in b1

        // P_s = T^2
        split_p_kernel<<<sg, sb>>>(0);                             // T -> PA + PBT
        gemm_hmma<<<gg, 256>>>(0, -1, 2, 1.0f);                    // b2 = T*T

        int s = 1, p = 2, f = 0;
        for (int it = 0; it < 8; it++) {
            float sigma = powf(0.95f, (float)(1 << (it + 1)));     // 0.95^(2^(it+1))
            split_p_kernel<<<sg, sb>>>(p);                         // P -> PA + PBT
            split_s_kernel<<<sg, sb>>>(s);                         // S -> SBT
            gemm_hmma<<<gg, 256>>>(1, s, f, sigma);                // S' = sigma*P*S + S
            if (it < 7) {
                gemm_hmma<<<gg, 256>>>(0, -1, s, 1.0f);            // P' = P*P
                int ns = f, np = s, nf = p;
                s = ns; p = np; f = nf;
            } else {
                s = f;
            }
        }

        int t = (s + 1) % 3;
        transpose_kernel<<<sg, sb>>>(s, t);
        topk_kernel<<<CH * NN, 512>>>(t, out, c0);
    }
}